// round 1
// baseline (speedup 1.0000x reference)
#include <cuda_runtime.h>
#include <cstdint>

// Problem constants
#define HIDDEN   1024
#define NUM_HEADS 16
#define HEAD_SZ   64      // HIDDEN / NUM_HEADS
#define BATCH      2
#define SEQ     2048
#define MTOT    (BATCH * SEQ)          // 4096 rows
#define QKV_N   (3 * HIDDEN)           // 3072

// Scratch (allocation-free rule: __device__ globals)
__device__ float g_qkv[(size_t)MTOT * QKV_N];   // 48 MB
__device__ float g_av [(size_t)MTOT * HIDDEN];  // 16 MB

// ---------------------------------------------------------------------------
// SGEMM: C[M,N] = A[M,K] @ B[K,N] + bias[N]
// 128x128 block tile, BK=8, 256 threads, 8x8 per-thread micro-tile.
// M, N, K must be multiples of 128/128/8 (true for all calls here).
// ---------------------------------------------------------------------------
__global__ __launch_bounds__(256) void sgemm_bias_kernel(
    const float* __restrict__ A, const float* __restrict__ B,
    const float* __restrict__ bias, float* __restrict__ C,
    int M, int N, int K)
{
    const int BM = 128, BN = 128, BK = 8;
    __shared__ float As[BK][BM];
    __shared__ float Bs[BK][BN];

    const int tid = threadIdx.x;
    const int row0 = blockIdx.y * BM;
    const int col0 = blockIdx.x * BN;

    // A-tile load mapping: 256 threads x float4 = 1024 floats = 128x8
    const int a_r = tid >> 1;            // 0..127 (row within tile)
    const int a_c = (tid & 1) * 4;       // 0 or 4 (k within tile)
    // B-tile load mapping: 8 rows x 128 cols
    const int b_r = tid >> 5;            // 0..7
    const int b_c = (tid & 31) * 4;      // 0..124

    const int tx = tid & 15;             // micro-tile col group
    const int ty = tid >> 4;             // micro-tile row group

    float acc[8][8];
#pragma unroll
    for (int i = 0; i < 8; i++)
#pragma unroll
        for (int j = 0; j < 8; j++) acc[i][j] = 0.0f;

    const float* Aptr = A + (size_t)(row0 + a_r) * K + a_c;
    const float* Bptr = B + (size_t)b_r * N + col0 + b_c;

    for (int k0 = 0; k0 < K; k0 += BK) {
        float4 av = *(const float4*)Aptr;
        float4 bv = *(const float4*)Bptr;
        Aptr += BK;
        Bptr += (size_t)BK * N;

        As[a_c + 0][a_r] = av.x;
        As[a_c + 1][a_r] = av.y;
        As[a_c + 2][a_r] = av.z;
        As[a_c + 3][a_r] = av.w;
        *(float4*)&Bs[b_r][b_c] = bv;
        __syncthreads();

#pragma unroll
        for (int k = 0; k < BK; k++) {
            float4 a0 = *(const float4*)&As[k][ty * 8];
            float4 a1 = *(const float4*)&As[k][ty * 8 + 4];
            float4 b0 = *(const float4*)&Bs[k][tx * 8];
            float4 b1 = *(const float4*)&Bs[k][tx * 8 + 4];
            float af[8] = {a0.x, a0.y, a0.z, a0.w, a1.x, a1.y, a1.z, a1.w};
            float bf[8] = {b0.x, b0.y, b0.z, b0.w, b1.x, b1.y, b1.z, b1.w};
#pragma unroll
            for (int i = 0; i < 8; i++)
#pragma unroll
                for (int j = 0; j < 8; j++)
                    acc[i][j] = fmaf(af[i], bf[j], acc[i][j]);
        }
        __syncthreads();
    }

    // Epilogue with bias
#pragma unroll
    for (int i = 0; i < 8; i++) {
        const int r = row0 + ty * 8 + i;
        float* crow = C + (size_t)r * N + col0 + tx * 8;
#pragma unroll
        for (int j = 0; j < 8; j += 4) {
            float4 o;
            o.x = acc[i][j + 0] + bias[col0 + tx * 8 + j + 0];
            o.y = acc[i][j + 1] + bias[col0 + tx * 8 + j + 1];
            o.z = acc[i][j + 2] + bias[col0 + tx * 8 + j + 2];
            o.w = acc[i][j + 3] + bias[col0 + tx * 8 + j + 3];
            *(float4*)(crow + j) = o;
        }
    }
}

// ---------------------------------------------------------------------------
// Flash-style attention over g_qkv.
// Grid: (SEQ/128, BATCH*NUM_HEADS). 128 threads, thread-per-query.
// q row and O accumulator in registers; K/V tiles (32x64) in smem.
// Layout: g_qkv[(b*SEQ + s)*3072 + {0,1024,2048} + h*64 + d]
// Output: g_av[(b*SEQ + s)*1024 + h*64 + d]
// ---------------------------------------------------------------------------
#define KT 32   // key tile

__global__ __launch_bounds__(128, 2) void flash_attn_kernel()
{
    __shared__ float Ks[KT][HEAD_SZ];
    __shared__ float Vs[KT][HEAD_SZ];

    const int tid = threadIdx.x;
    const int bh = blockIdx.y;
    const int b = bh >> 4;
    const int h = bh & 15;
    const int qi = blockIdx.x * 128 + tid;

    const float* base = g_qkv + (size_t)b * SEQ * QKV_N;
    const float* qrow = base + (size_t)qi * QKV_N + h * HEAD_SZ;

    const float scale = 0.125f;  // 1/sqrt(64)

    float q[HEAD_SZ];
#pragma unroll
    for (int i = 0; i < HEAD_SZ / 4; i++) {
        float4 v = *(const float4*)(qrow + i * 4);
        q[4 * i + 0] = v.x * scale;
        q[4 * i + 1] = v.y * scale;
        q[4 * i + 2] = v.z * scale;
        q[4 * i + 3] = v.w * scale;
    }

    float o[HEAD_SZ];
#pragma unroll
    for (int d = 0; d < HEAD_SZ; d++) o[d] = 0.0f;
    float m = -1e30f;
    float l = 0.0f;

    for (int kb = 0; kb < SEQ; kb += KT) {
        // Cooperative load of K and V tiles (KT*64 floats each = 512 float4)
        __syncthreads();
#pragma unroll
        for (int it = 0; it < (KT * HEAD_SZ / 4) / 128; it++) {
            int idx = it * 128 + tid;            // 0..511
            int r = idx >> 4;                    // 0..31
            int c4 = (idx & 15) * 4;             // 0..60
            const float* krow = base + (size_t)(kb + r) * QKV_N + HIDDEN + h * HEAD_SZ + c4;
            const float* vrow = base + (size_t)(kb + r) * QKV_N + 2 * HIDDEN + h * HEAD_SZ + c4;
            *(float4*)&Ks[r][c4] = *(const float4*)krow;
            *(float4*)&Vs[r][c4] = *(const float4*)vrow;
        }
        __syncthreads();

        // Scores for this tile
        float s[KT];
        float tmax = -1e30f;
#pragma unroll
        for (int j = 0; j < KT; j++) {
            float acc = 0.0f;
#pragma unroll
            for (int d = 0; d < HEAD_SZ; d += 4) {
                float4 kv = *(const float4*)&Ks[j][d];
                acc = fmaf(q[d + 0], kv.x, acc);
                acc = fmaf(q[d + 1], kv.y, acc);
                acc = fmaf(q[d + 2], kv.z, acc);
                acc = fmaf(q[d + 3], kv.w, acc);
            }
            s[j] = acc;
            tmax = fmaxf(tmax, acc);
        }

        // Online softmax update
        const float m_new = fmaxf(m, tmax);
        const float alpha = __expf(m - m_new);
        m = m_new;
        l *= alpha;
#pragma unroll
        for (int d = 0; d < HEAD_SZ; d++) o[d] *= alpha;

#pragma unroll
        for (int j = 0; j < KT; j++) {
            const float p = __expf(s[j] - m_new);
            l += p;
#pragma unroll
            for (int d = 0; d < HEAD_SZ; d += 4) {
                float4 vv = *(const float4*)&Vs[j][d];
                o[d + 0] = fmaf(p, vv.x, o[d + 0]);
                o[d + 1] = fmaf(p, vv.y, o[d + 1]);
                o[d + 2] = fmaf(p, vv.z, o[d + 2]);
                o[d + 3] = fmaf(p, vv.w, o[d + 3]);
            }
        }
    }

    const float inv_l = 1.0f / l;
    float* orow = g_av + (size_t)(b * SEQ + qi) * HIDDEN + h * HEAD_SZ;
#pragma unroll
    for (int d = 0; d < HEAD_SZ; d += 4) {
        float4 ov;
        ov.x = o[d + 0] * inv_l;
        ov.y = o[d + 1] * inv_l;
        ov.z = o[d + 2] * inv_l;
        ov.w = o[d + 3] * inv_l;
        *(float4*)(orow + d) = ov;
    }
}

// ---------------------------------------------------------------------------
// Launch: qkv GEMM -> flash attention -> output GEMM
// Inputs (metadata order): x, W_qkv, b_qkv, W_o, b_o
// ---------------------------------------------------------------------------
extern "C" void kernel_launch(void* const* d_in, const int* in_sizes, int n_in,
                              void* d_out, int out_size)
{
    const float* x     = (const float*)d_in[0];
    const float* W_qkv = (const float*)d_in[1];
    const float* b_qkv = (const float*)d_in[2];
    const float* W_o   = (const float*)d_in[3];
    const float* b_o   = (const float*)d_in[4];
    float* out = (float*)d_out;

    float* qkv;
    float* av;
    cudaGetSymbolAddress((void**)&qkv, g_qkv);
    cudaGetSymbolAddress((void**)&av, g_av);

    // 1) qkv = x @ W_qkv + b_qkv   [4096 x 3072]
    {
        dim3 grid(QKV_N / 128, MTOT / 128);
        sgemm_bias_kernel<<<grid, 256>>>(x, W_qkv, b_qkv, qkv, MTOT, QKV_N, HIDDEN);
    }

    // 2) attention -> av  [4096 x 1024]
    {
        dim3 grid(SEQ / 128, BATCH * NUM_HEADS);
        flash_attn_kernel<<<grid, 128>>>();
    }

    // 3) out = av @ W_o + b_o  [4096 x 1024]
    {
        dim3 grid(HIDDEN / 128, MTOT / 128);
        sgemm_bias_kernel<<<grid, 256>>>(av, W_o, b_o, out, MTOT, HIDDEN, HIDDEN);
    }
}

// round 2
// speedup vs baseline: 3.7351x; 3.7351x over previous
#include <cuda_runtime.h>
#include <cstdint>

#define HIDDEN   1024
#define NUM_HEADS 16
#define HEAD_SZ   64
#define BATCH      2
#define SEQ     2048
#define MTOT    (BATCH * SEQ)          // 4096
#define QKV_N   (3 * HIDDEN)           // 3072

// Scratch (allocation-free rule: __device__ globals)
__device__ float g_qkv[(size_t)MTOT * QKV_N];   // 48 MB
__device__ float g_av [(size_t)MTOT * HIDDEN];  // 16 MB

// ---------------------------------------------------------------------------
// tf32 helpers
// ---------------------------------------------------------------------------
__device__ __forceinline__ uint32_t f2tf(float x) {
    uint32_t r;
    asm("cvt.rna.tf32.f32 %0, %1;" : "=r"(r) : "f"(x));
    return r;
}
__device__ __forceinline__ float f2tf_f(float x) { return __uint_as_float(f2tf(x)); }

__device__ __forceinline__ void mma_tf32(float c[4],
    uint32_t a0, uint32_t a1, uint32_t a2, uint32_t a3,
    uint32_t b0, uint32_t b1)
{
    asm volatile(
        "mma.sync.aligned.m16n8k8.row.col.f32.tf32.tf32.f32 "
        "{%0,%1,%2,%3}, {%4,%5,%6,%7}, {%8,%9}, {%0,%1,%2,%3};\n"
        : "+f"(c[0]), "+f"(c[1]), "+f"(c[2]), "+f"(c[3])
        : "r"(a0), "r"(a1), "r"(a2), "r"(a3), "r"(b0), "r"(b1));
}

// ---------------------------------------------------------------------------
// TF32 GEMM: C[M,N] = A[M,K] @ B[K,N] + bias
// Block 128x128, BK=32, 256 threads = 8 warps (2 x 4), warp tile 64x32.
// ---------------------------------------------------------------------------
__global__ __launch_bounds__(256) void gemm_tf32(
    const float* __restrict__ A, const float* __restrict__ B,
    const float* __restrict__ bias, float* __restrict__ C,
    int M, int N, int K)
{
    __shared__ float As[128][36];   // pitch 36: conflict-free frag reads
    __shared__ float Bs[32][136];   // pitch 136: conflict-free frag reads

    const int tid  = threadIdx.x;
    const int warp = tid >> 5, lane = tid & 31;
    const int wm = warp >> 2, wn = warp & 3;      // 2 x 4 warp grid
    const int g = lane >> 2, tig = lane & 3;
    const int row0 = blockIdx.y * 128, col0 = blockIdx.x * 128;

    const float* Ag = A + (size_t)row0 * K;
    const float* Bg = B + col0;

    const int a_r = tid >> 3, a_c = (tid & 7) * 4;   // + p*32 rows
    const int b_r = tid >> 5, b_c = (tid & 31) * 4;  // + p*8 rows

    float acc[4][4][4];
#pragma unroll
    for (int mt = 0; mt < 4; mt++)
#pragma unroll
        for (int nt = 0; nt < 4; nt++)
#pragma unroll
            for (int i = 0; i < 4; i++) acc[mt][nt][i] = 0.0f;

    float4 aS[4], bS[4];

    // prologue load k0 = 0
#pragma unroll
    for (int p = 0; p < 4; p++) {
        aS[p] = *(const float4*)(Ag + (size_t)(p * 32 + a_r) * K + a_c);
        bS[p] = *(const float4*)(Bg + (size_t)(p * 8 + b_r) * N + b_c);
    }
#pragma unroll
    for (int p = 0; p < 4; p++) {
        float4 a = aS[p], b = bS[p];
        float4 ac4 = make_float4(f2tf_f(a.x), f2tf_f(a.y), f2tf_f(a.z), f2tf_f(a.w));
        float4 bc4 = make_float4(f2tf_f(b.x), f2tf_f(b.y), f2tf_f(b.z), f2tf_f(b.w));
        *(float4*)&As[p * 32 + a_r][a_c] = ac4;
        *(float4*)&Bs[p * 8 + b_r][b_c] = bc4;
    }
    __syncthreads();

    for (int k0 = 0; k0 < K; k0 += 32) {
        const bool more = (k0 + 32) < K;
        if (more) {
#pragma unroll
            for (int p = 0; p < 4; p++) {
                aS[p] = *(const float4*)(Ag + (size_t)(p * 32 + a_r) * K + k0 + 32 + a_c);
                bS[p] = *(const float4*)(Bg + (size_t)(k0 + 32 + p * 8 + b_r) * N + b_c);
            }
        }

#pragma unroll
        for (int kk = 0; kk < 4; kk++) {
            uint32_t af[4][4], bf[4][2];
            const int cA = kk * 8 + tig;
#pragma unroll
            for (int mt = 0; mt < 4; mt++) {
                const int r = wm * 64 + mt * 16 + g;
                af[mt][0] = __float_as_uint(As[r][cA]);
                af[mt][1] = __float_as_uint(As[r + 8][cA]);
                af[mt][2] = __float_as_uint(As[r][cA + 4]);
                af[mt][3] = __float_as_uint(As[r + 8][cA + 4]);
            }
#pragma unroll
            for (int nt = 0; nt < 4; nt++) {
                const int cB = wn * 32 + nt * 8 + g;
                bf[nt][0] = __float_as_uint(Bs[kk * 8 + tig][cB]);
                bf[nt][1] = __float_as_uint(Bs[kk * 8 + tig + 4][cB]);
            }
#pragma unroll
            for (int mt = 0; mt < 4; mt++)
#pragma unroll
                for (int nt = 0; nt < 4; nt++)
                    mma_tf32(acc[mt][nt], af[mt][0], af[mt][1], af[mt][2], af[mt][3],
                             bf[nt][0], bf[nt][1]);
        }
        __syncthreads();
        if (more) {
#pragma unroll
            for (int p = 0; p < 4; p++) {
                float4 a = aS[p], b = bS[p];
                float4 ac4 = make_float4(f2tf_f(a.x), f2tf_f(a.y), f2tf_f(a.z), f2tf_f(a.w));
                float4 bc4 = make_float4(f2tf_f(b.x), f2tf_f(b.y), f2tf_f(b.z), f2tf_f(b.w));
                *(float4*)&As[p * 32 + a_r][a_c] = ac4;
                *(float4*)&Bs[p * 8 + b_r][b_c] = bc4;
            }
            __syncthreads();
        }
    }

    // Epilogue with bias (c0,c1 at row g; c2,c3 at row g+8; cols tig*2, tig*2+1)
#pragma unroll
    for (int mt = 0; mt < 4; mt++) {
        const int r_lo = row0 + wm * 64 + mt * 16 + g;
        const int r_hi = r_lo + 8;
#pragma unroll
        for (int nt = 0; nt < 4; nt++) {
            const int col = col0 + wn * 32 + nt * 8 + tig * 2;
            const float b0 = bias[col], b1 = bias[col + 1];
            float2 lo = make_float2(acc[mt][nt][0] + b0, acc[mt][nt][1] + b1);
            float2 hi = make_float2(acc[mt][nt][2] + b0, acc[mt][nt][3] + b1);
            *(float2*)(C + (size_t)r_lo * N + col) = lo;
            *(float2*)(C + (size_t)r_hi * N + col) = hi;
        }
    }
}

// ---------------------------------------------------------------------------
// TF32 flash attention.
// Grid: (SEQ/128, BATCH*NUM_HEADS), 256 threads = 8 warps.
// Warp w owns query rows [w*16, w*16+16) of the 128-query tile -> softmax
// rows never cross warps. Q fragments persist in registers; K/V 64-key
// tiles staged in smem (tf32). Scores->P layout fix via register shuffles.
// ---------------------------------------------------------------------------
__global__ __launch_bounds__(256) void attn_tf32()
{
    // Pool: Ks[64][68] + Vs[64][72]  (8960 floats). Qs[128][68] aliases pool
    // during the prologue only (8704 <= 8960).
    __shared__ float pool[64 * 68 + 64 * 72];
    float (*Ks)[68] = (float(*)[68])pool;
    float (*Vs)[72] = (float(*)[72])(pool + 64 * 68);
    float (*Qs)[68] = (float(*)[68])pool;

    const int tid = threadIdx.x;
    const int warp = tid >> 5, lane = tid & 31;
    const int g = lane >> 2, tig = lane & 3;
    const int bh = blockIdx.y;
    const int b = bh >> 4, h = bh & 15;
    const int q0 = blockIdx.x * 128;

    const float* base = g_qkv + (size_t)b * SEQ * QKV_N;

    // ---- Prologue: load Q tile (scaled by 1/sqrt(64), tf32) ----
    {
        const int r = tid >> 4, c4 = (tid & 15) * 4;
#pragma unroll
        for (int p = 0; p < 8; p++) {
            const int row = p * 16 + r;
            float4 v = *(const float4*)(base + (size_t)(q0 + row) * QKV_N + h * HEAD_SZ + c4);
            float4 s = make_float4(f2tf_f(v.x * 0.125f), f2tf_f(v.y * 0.125f),
                                   f2tf_f(v.z * 0.125f), f2tf_f(v.w * 0.125f));
            *(float4*)&Qs[row][c4] = s;
        }
    }
    __syncthreads();

    // Build Q fragments: 8 k-steps (d = 0..63), rows warp*16 + g (+8)
    uint32_t qf[8][4];
    {
        const int rb = warp * 16;
#pragma unroll
        for (int ks = 0; ks < 8; ks++) {
            const int c = ks * 8 + tig;
            qf[ks][0] = __float_as_uint(Qs[rb + g][c]);
            qf[ks][1] = __float_as_uint(Qs[rb + 8 + g][c]);
            qf[ks][2] = __float_as_uint(Qs[rb + g][c + 4]);
            qf[ks][3] = __float_as_uint(Qs[rb + 8 + g][c + 4]);
        }
    }
    __syncthreads();   // pool will be overwritten by K/V

    float o[8][4];
#pragma unroll
    for (int nt = 0; nt < 8; nt++)
#pragma unroll
        for (int i = 0; i < 4; i++) o[nt][i] = 0.0f;
    float m_lo = -1e30f, m_hi = -1e30f;
    float l_lo = 0.0f, l_hi = 0.0f;

    const int lr = tid >> 4, lc4 = (tid & 15) * 4;

    for (int kb = 0; kb < SEQ; kb += 64) {
        // ---- Load K and V tiles (64 x 64 each), tf32 ----
#pragma unroll
        for (int p = 0; p < 4; p++) {
            const int row = p * 16 + lr;
            const float* kr = base + (size_t)(kb + row) * QKV_N + HIDDEN + h * HEAD_SZ + lc4;
            const float* vr = base + (size_t)(kb + row) * QKV_N + 2 * HIDDEN + h * HEAD_SZ + lc4;
            float4 kv = *(const float4*)kr;
            float4 vv = *(const float4*)vr;
            *(float4*)&Ks[row][lc4] = make_float4(f2tf_f(kv.x), f2tf_f(kv.y), f2tf_f(kv.z), f2tf_f(kv.w));
            *(float4*)&Vs[row][lc4] = make_float4(f2tf_f(vv.x), f2tf_f(vv.y), f2tf_f(vv.z), f2tf_f(vv.w));
        }
        __syncthreads();

        // ---- S = Q @ K^T : per warp 16 x 64, 8 key-tiles of 8 ----
        float c[8][4];
#pragma unroll
        for (int nt = 0; nt < 8; nt++) {
            c[nt][0] = c[nt][1] = c[nt][2] = c[nt][3] = 0.0f;
#pragma unroll
            for (int ks = 0; ks < 8; ks++) {
                uint32_t b0 = __float_as_uint(Ks[nt * 8 + g][ks * 8 + tig]);
                uint32_t b1 = __float_as_uint(Ks[nt * 8 + g][ks * 8 + tig + 4]);
                mma_tf32(c[nt], qf[ks][0], qf[ks][1], qf[ks][2], qf[ks][3], b0, b1);
            }
        }

        // ---- Online softmax: row max (rows = g and g+8, shared by 4-lane group) ----
        float tmx_lo = -1e30f, tmx_hi = -1e30f;
#pragma unroll
        for (int nt = 0; nt < 8; nt++) {
            tmx_lo = fmaxf(tmx_lo, fmaxf(c[nt][0], c[nt][1]));
            tmx_hi = fmaxf(tmx_hi, fmaxf(c[nt][2], c[nt][3]));
        }
        tmx_lo = fmaxf(tmx_lo, __shfl_xor_sync(0xffffffffu, tmx_lo, 1));
        tmx_lo = fmaxf(tmx_lo, __shfl_xor_sync(0xffffffffu, tmx_lo, 2));
        tmx_hi = fmaxf(tmx_hi, __shfl_xor_sync(0xffffffffu, tmx_hi, 1));
        tmx_hi = fmaxf(tmx_hi, __shfl_xor_sync(0xffffffffu, tmx_hi, 2));

        const float mn_lo = fmaxf(m_lo, tmx_lo);
        const float mn_hi = fmaxf(m_hi, tmx_hi);
        const float al_lo = __expf(m_lo - mn_lo);
        const float al_hi = __expf(m_hi - mn_hi);
        m_lo = mn_lo; m_hi = mn_hi;
        l_lo *= al_lo; l_hi *= al_hi;
#pragma unroll
        for (int nt = 0; nt < 8; nt++) {
            o[nt][0] *= al_lo; o[nt][1] *= al_lo;
            o[nt][2] *= al_hi; o[nt][3] *= al_hi;
        }

        // ---- P @ V : for each 8-key chunk, shuffle scores into A-frag layout ----
        const int srcA = (lane & ~3) | (tig >> 1);
        const int srcB = srcA | 2;
        const bool oddc = (tig & 1);
#pragma unroll
        for (int ks = 0; ks < 8; ks++) {
            float v00 = __shfl_sync(0xffffffffu, c[ks][0], srcA);
            float v01 = __shfl_sync(0xffffffffu, c[ks][1], srcA);
            float w00 = __shfl_sync(0xffffffffu, c[ks][0], srcB);
            float w01 = __shfl_sync(0xffffffffu, c[ks][1], srcB);
            float v10 = __shfl_sync(0xffffffffu, c[ks][2], srcA);
            float v11 = __shfl_sync(0xffffffffu, c[ks][3], srcA);
            float w10 = __shfl_sync(0xffffffffu, c[ks][2], srcB);
            float w11 = __shfl_sync(0xffffffffu, c[ks][3], srcB);

            float s0 = oddc ? v01 : v00;   // row g,   key tig
            float s2 = oddc ? w01 : w00;   // row g,   key tig+4
            float s1 = oddc ? v11 : v10;   // row g+8, key tig
            float s3 = oddc ? w11 : w10;   // row g+8, key tig+4

            float p0 = __expf(s0 - m_lo);
            float p2 = __expf(s2 - m_lo);
            float p1 = __expf(s1 - m_hi);
            float p3 = __expf(s3 - m_hi);
            l_lo += p0 + p2;
            l_hi += p1 + p3;

            uint32_t a0 = f2tf(p0), a1 = f2tf(p1), a2 = f2tf(p2), a3 = f2tf(p3);
#pragma unroll
            for (int nd = 0; nd < 8; nd++) {
                uint32_t b0 = __float_as_uint(Vs[ks * 8 + tig][nd * 8 + g]);
                uint32_t b1 = __float_as_uint(Vs[ks * 8 + tig + 4][nd * 8 + g]);
                mma_tf32(o[nd], a0, a1, a2, a3, b0, b1);
            }
        }
        __syncthreads();   // before next tile overwrites Ks/Vs
    }

    // ---- Final normalization + store ----
    l_lo += __shfl_xor_sync(0xffffffffu, l_lo, 1);
    l_lo += __shfl_xor_sync(0xffffffffu, l_lo, 2);
    l_hi += __shfl_xor_sync(0xffffffffu, l_hi, 1);
    l_hi += __shfl_xor_sync(0xffffffffu, l_hi, 2);
    const float inv_lo = 1.0f / l_lo;
    const float inv_hi = 1.0f / l_hi;

    const int r_lo = q0 + warp * 16 + g;
    const int r_hi = r_lo + 8;
    float* avb = g_av + (size_t)b * SEQ * HIDDEN + h * HEAD_SZ;
#pragma unroll
    for (int nd = 0; nd < 8; nd++) {
        const int col = nd * 8 + tig * 2;
        *(float2*)(avb + (size_t)r_lo * HIDDEN + col) =
            make_float2(o[nd][0] * inv_lo, o[nd][1] * inv_lo);
        *(float2*)(avb + (size_t)r_hi * HIDDEN + col) =
            make_float2(o[nd][2] * inv_hi, o[nd][3] * inv_hi);
    }
}

// ---------------------------------------------------------------------------
// Launch
// ---------------------------------------------------------------------------
extern "C" void kernel_launch(void* const* d_in, const int* in_sizes, int n_in,
                              void* d_out, int out_size)
{
    const float* x     = (const float*)d_in[0];
    const float* W_qkv = (const float*)d_in[1];
    const float* b_qkv = (const float*)d_in[2];
    const float* W_o   = (const float*)d_in[3];
    const float* b_o   = (const float*)d_in[4];
    float* out = (float*)d_out;

    float* qkv;
    float* av;
    cudaGetSymbolAddress((void**)&qkv, g_qkv);
    cudaGetSymbolAddress((void**)&av, g_av);

    // 1) qkv = x @ W_qkv + b_qkv   [4096 x 3072]
    {
        dim3 grid(QKV_N / 128, MTOT / 128);
        gemm_tf32<<<grid, 256>>>(x, W_qkv, b_qkv, qkv, MTOT, QKV_N, HIDDEN);
    }
    // 2) attention -> av  [4096 x 1024]
    {
        dim3 grid(SEQ / 128, BATCH * NUM_HEADS);
        attn_tf32<<<grid, 256>>>();
    }
    // 3) out = av @ W_o + b_o  [4096 x 1024]
    {
        dim3 grid(HIDDEN / 128, MTOT / 128);
        gemm_tf32<<<grid, 256>>>(av, W_o, b_o, out, MTOT, HIDDEN, HIDDEN);
    }
}